// round 7
// baseline (speedup 1.0000x reference)
#include <cuda_runtime.h>
#include <cuda_fp16.h>
#include <cuda_bf16.h>
#include <cstdint>

#define ABLK  528
#define ASZ   4224       // 8 A-blocks * 528B per variant
#define AOFF2 8448       // 2*ASZ
#define BSZ   16384
#define STG   41216      // AOFF2 + 2*BSZ
#define PSTR  264        // half elems per P row
#define OFF_LB 33792     // = 64*264*2 (P bytes); leaf buffers follow
#define SMEM_DYN 99328   // OFF_LB + 2*32768

static __device__ __nv_bfloat16 g_Wf_hi[262144];
static __device__ __nv_bfloat16 g_Wf_lo[262144];
static __device__ __nv_bfloat16 g_Lf_hi[32768];
static __device__ __nv_bfloat16 g_Lf_lo[32768];

__device__ __forceinline__ uint32_t smem_u32(const void* p) {
    uint32_t a;
    asm("{ .reg .u64 t; cvta.to.shared.u64 t, %1; cvt.u32.u64 %0, t; }" : "=r"(a) : "l"(p));
    return a;
}
__device__ __forceinline__ void cp16(uint32_t dst, const void* src) {
    asm volatile("cp.async.cg.shared.global [%0], [%1], 16;" :: "r"(dst), "l"(src) : "memory");
}
#define CP_COMMIT() asm volatile("cp.async.commit_group;" ::: "memory")
#define CP_WAIT0()  asm volatile("cp.async.wait_group 0;" ::: "memory")

__device__ __forceinline__ void mma_bf16(float* c, const uint32_t* a, uint32_t b0, uint32_t b1) {
    asm volatile("mma.sync.aligned.m16n8k16.row.col.f32.bf16.bf16.f32 "
        "{%0,%1,%2,%3}, {%4,%5,%6,%7}, {%8,%9}, {%0,%1,%2,%3};"
        : "+f"(c[0]), "+f"(c[1]), "+f"(c[2]), "+f"(c[3])
        : "r"(a[0]), "r"(a[1]), "r"(a[2]), "r"(a[3]), "r"(b0), "r"(b1));
}
__device__ __forceinline__ uint32_t pack_bf2(float a, float b) {
    __nv_bfloat162 t = __floats2bfloat162_rn(a, b);
    return *reinterpret_cast<uint32_t*>(&t);
}
__device__ __forceinline__ void split_pk(float pe, float po, uint32_t& hi, uint32_t& lo) {
    __nv_bfloat16 he = __float2bfloat16(pe), ho = __float2bfloat16(po);
    hi = pack_bf2(__bfloat162float(he), __bfloat162float(ho));
    lo = pack_bf2(pe - __bfloat162float(he), po - __bfloat162float(ho));
}

// W[k][n] -> frag-linear bf16 hi/lo, 32 K-chunks, paired n-tiles (uint4 = 2 nt frags)
__global__ void prep_w(const float* __restrict__ W) {
    int idx = blockIdx.x * 256 + threadIdx.x;
    int k = idx >> 8, n = idx & 255;
    float v = (n < 255) ? W[k * 255 + n] : 0.0f;
    __nv_bfloat16 h = __float2bfloat16(v);
    __nv_bfloat16 l = __float2bfloat16(v - __bfloat162float(h));
    int chunk = k >> 5, kin = k & 31, s = kin >> 4, kk = kin & 15;
    int nt = n >> 3, pr = nt >> 1, e = nt & 1;
    int tl = (n & 7) * 4 + ((kk >> 1) & 3), rg = kk >> 3, hf = kk & 1;
    int o = chunk * 8192 + s * 4096 + pr * 256 + tl * 8 + e * 4 + rg * 2 + hf;
    g_Wf_hi[o] = h; g_Wf_lo[o] = l;
}
// leaf[k][n] (256 leaves x 128 dout) -> frag-linear, paired n-tiles
__global__ void prep_leaf(const float* __restrict__ L) {
    int idx = blockIdx.x * 256 + threadIdx.x;
    int k = idx >> 7, n = idx & 127;
    float v = L[k * 128 + n];
    __nv_bfloat16 h = __float2bfloat16(v);
    __nv_bfloat16 l = __float2bfloat16(v - __bfloat162float(h));
    int s = k >> 4, kk = k & 15;
    int nt = n >> 3, pr = nt >> 1, e = nt & 1;
    int tl = (n & 7) * 4 + ((kk >> 1) & 3), rg = kk >> 3, hf = kk & 1;
    int o = s * 2048 + pr * 256 + tl * 8 + e * 4 + rg * 2 + hf;
    g_Lf_hi[o] = h; g_Lf_lo[o] = l;
}
__global__ void init_reg(float* regp) { *regp = 0.0f; }

__global__ void __launch_bounds__(256, 2) tree_main(
    const float* __restrict__ x, const float* __restrict__ bsp,
    float* __restrict__ out, float* __restrict__ regp)
{
    extern __shared__ char smc[];
    __shared__ float s_bias[256];
    __shared__ float s_racc;
    const uint32_t sb = smem_u32(smc);

    const int tid = threadIdx.x, lane = tid & 31, w = tid >> 5;
    const int mwarp = w & 1, nwarp = w >> 1;          // 32-row x 64-col warp tile
    const int m0 = blockIdx.x * 64;

    s_bias[tid] = (tid < 255) ? bsp[tid] : 0.0f;
    if (tid == 0) s_racc = 0.0f;

    float acc[2][8][4] = {};

    const int r = tid >> 2;             // staging row 0..63
    const int ko = (tid & 3) * 8;       // 8 consecutive k per thread

    // ---- prologue: chunk 0 ----
    {
        const float* xp = x + (size_t)(m0 + r) * 1024 + ko;
        float fv[8];
        *(float4*)(fv)     = *(const float4*)xp;
        *(float4*)(fv + 4) = *(const float4*)(xp + 4);
        #pragma unroll
        for (int i = 0; i < 4; i++) {
            cp16(sb + AOFF2 + (tid + i * 256) * 16, (const char*)g_Wf_hi + (tid + i * 256) * 16);
            cp16(sb + AOFF2 + BSZ + (tid + i * 256) * 16, (const char*)g_Wf_lo + (tid + i * 256) * 16);
        }
        CP_COMMIT();
        #pragma unroll
        for (int q = 0; q < 4; q++) {
            int p = (tid & 3) * 4 + q;
            int s = p >> 3, pp = p & 7;
            int o = (s * 4 + (r >> 4)) * ABLK + (4 * (r & 7) + (pp & 3)) * 16
                    + (((r >> 3) & 1) + ((pp >> 2) << 1)) * 4;
            uint32_t hv, lv;
            split_pk(fv[2 * q], fv[2 * q + 1], hv, lv);
            *(uint32_t*)(smc + o) = hv;
            *(uint32_t*)(smc + o + ASZ) = lv;
        }
    }

    // ---- GEMM1: 32 K-chunks, double-buffered ----
    for (int c = 0; c < 32; c++) {
        const int st = c & 1, nst = st ^ 1;
        float fv[8];
        if (c < 31) {   // x prefetch before the wait: LDG latency overlaps drain
            const float* xp = x + (size_t)(m0 + r) * 1024 + (c + 1) * 32 + ko;
            *(float4*)(fv)     = *(const float4*)xp;
            *(float4*)(fv + 4) = *(const float4*)(xp + 4);
        }
        CP_WAIT0();
        __syncthreads();
        if (c < 31) {
            const char* srcH = (const char*)g_Wf_hi + (c + 1) * 16384;
            const char* srcL = (const char*)g_Wf_lo + (c + 1) * 16384;
            #pragma unroll
            for (int i = 0; i < 4; i++) {
                cp16(sb + nst * STG + AOFF2 + (tid + i * 256) * 16, srcH + (tid + i * 256) * 16);
                cp16(sb + nst * STG + AOFF2 + BSZ + (tid + i * 256) * 16, srcL + (tid + i * 256) * 16);
            }
            CP_COMMIT();
        }
        #pragma unroll
        for (int s = 0; s < 2; s++) {
            uint32_t ah[2][4], al[2][4];
            #pragma unroll
            for (int mt = 0; mt < 2; mt++) {
                const char* ap = smc + st * STG + (s * 4 + mwarp * 2 + mt) * ABLK + lane * 16;
                *(uint4*)ah[mt] = *(const uint4*)ap;
                *(uint4*)al[mt] = *(const uint4*)(ap + ASZ);
            }
            #pragma unroll
            for (int ntp = 0; ntp < 4; ntp++) {
                const char* bp = smc + st * STG + AOFF2 + s * 8192 + (nwarp * 4 + ntp) * 512 + lane * 16;
                uint4 bh = *(const uint4*)bp;
                uint4 bl = *(const uint4*)(bp + BSZ);
                // pass-major: same-acc dependency distance = 4 issues (~32 cyc)
                mma_bf16(acc[0][2 * ntp],     ah[0], bh.x, bh.y);
                mma_bf16(acc[0][2 * ntp + 1], ah[0], bh.z, bh.w);
                mma_bf16(acc[1][2 * ntp],     ah[1], bh.x, bh.y);
                mma_bf16(acc[1][2 * ntp + 1], ah[1], bh.z, bh.w);
                mma_bf16(acc[0][2 * ntp],     ah[0], bl.x, bl.y);
                mma_bf16(acc[0][2 * ntp + 1], ah[0], bl.z, bl.w);
                mma_bf16(acc[1][2 * ntp],     ah[1], bl.x, bl.y);
                mma_bf16(acc[1][2 * ntp + 1], ah[1], bl.z, bl.w);
                mma_bf16(acc[0][2 * ntp],     al[0], bh.x, bh.y);
                mma_bf16(acc[0][2 * ntp + 1], al[0], bh.z, bh.w);
                mma_bf16(acc[1][2 * ntp],     al[1], bh.x, bh.y);
                mma_bf16(acc[1][2 * ntp + 1], al[1], bh.z, bh.w);
            }
        }
        if (c < 31) {
            #pragma unroll
            for (int q = 0; q < 4; q++) {
                int p = (tid & 3) * 4 + q;
                int s = p >> 3, pp = p & 7;
                int o = nst * STG + (s * 4 + (r >> 4)) * ABLK + (4 * (r & 7) + (pp & 3)) * 16
                        + (((r >> 3) & 1) + ((pp >> 2) << 1)) * 4;
                uint32_t hv, lv;
                split_pk(fv[2 * q], fv[2 * q + 1], hv, lv);
                *(uint32_t*)(smc + o) = hv;
                *(uint32_t*)(smc + o + ASZ) = lv;
            }
        }
    }
    __syncthreads();   // GEMM1 regions dead

    // ---- prefetch leaf quarter 0, then sigmoid + reg; P -> SMEM fp16 ----
    #pragma unroll
    for (int i = 0; i < 4; i++) {
        cp16(sb + OFF_LB + (tid + i * 256) * 16, (const char*)g_Lf_hi + (tid + i * 256) * 16);
        cp16(sb + OFF_LB + 16384 + (tid + i * 256) * 16, (const char*)g_Lf_lo + (tid + i * 256) * 16);
    }
    CP_COMMIT();

    float racc = 0.0f;
    __half* Ph0 = (__half*)smc;
    #pragma unroll
    for (int mt = 0; mt < 2; mt++)
        #pragma unroll
        for (int nt = 0; nt < 8; nt++)
            #pragma unroll
            for (int cc = 0; cc < 4; cc++) {
                int row = mwarp * 32 + mt * 16 + (lane >> 2) + ((cc >> 1) << 3);
                int col = nwarp * 64 + nt * 8 + 2 * (lane & 3) + (cc & 1);
                if (col < 255) {
                    float lg = acc[mt][nt][cc] + s_bias[col];
                    float p = 1.0f / (1.0f + __expf(-lg));
                    Ph0[row * PSTR + col] = __float2half(p);
                    int d = 31 - __clz(col + 1);
                    racc += __uint_as_float((uint32_t)(127 - d) << 23) *
                            __logf(fmaxf(p * (1.0f - p), 1e-5f));
                }
            }

    // ---- GEMM2: tree-product A frags + leaf quarters (double-buffered) ----
    float acc2[8][4] = {};
    const int mwarp2 = w & 3, nwarp2 = w >> 2;
    const int la = lane & 3;
    #pragma unroll 1
    for (int qq = 0; qq < 4; qq++) {
        CP_WAIT0();
        __syncthreads();
        if (qq < 3) {
            uint32_t db = sb + OFF_LB + ((qq + 1) & 1) * 32768;
            const char* sh = (const char*)(g_Lf_hi + (qq + 1) * 8192);
            const char* sl = (const char*)(g_Lf_lo + (qq + 1) * 8192);
            #pragma unroll
            for (int i = 0; i < 4; i++) {
                cp16(db + (tid + i * 256) * 16, sh + (tid + i * 256) * 16);
                cp16(db + 16384 + (tid + i * 256) * 16, sl + (tid + i * 256) * 16);
            }
            CP_COMMIT();
        }
        const char* LB = smc + OFF_LB + (qq & 1) * 32768;
        #pragma unroll
        for (int sl2 = 0; sl2 < 4; sl2++) {
            int s = qq * 4 + sl2;
            int jA = 8 * s + la, jB = jA + 4;
            uint32_t ah[4], al4[4];
            #pragma unroll
            for (int rr = 0; rr < 2; rr++) {
                int row = mwarp2 * 16 + (lane >> 2) + rr * 8;
                const __half* Ph = Ph0 + row * PSTR;
                float pv, pre;
                pv = __half2float(Ph[s >> 4]);       pre  = ((s >> 3) & 1) ? pv : 1.0f - pv;
                pv = __half2float(Ph[1 + (s >> 3)]); pre *= ((s >> 2) & 1) ? pv : 1.0f - pv;
                pv = __half2float(Ph[3 + (s >> 2)]); pre *= ((s >> 1) & 1) ? pv : 1.0f - pv;
                pv = __half2float(Ph[7 + (s >> 1)]); pre *= (s & 1) ? pv : 1.0f - pv;
                float p4 = __half2float(Ph[15 + s]);
                float preA = pre * (1.0f - p4), preB = pre * p4;
                int b5 = (la >> 1) & 1, b6 = la & 1;
                float p5a = __half2float(Ph[31 + 2 * s]);
                float p5b = __half2float(Ph[31 + 2 * s + 1]);
                preA *= b5 ? p5a : 1.0f - p5a;
                preB *= b5 ? p5b : 1.0f - p5b;
                float p6a = __half2float(Ph[63 + (jA >> 1)]);
                float p6b = __half2float(Ph[63 + (jB >> 1)]);
                preA *= b6 ? p6a : 1.0f - p6a;
                preB *= b6 ? p6b : 1.0f - p6b;
                float p7a = __half2float(Ph[127 + jA]);
                float p7b = __half2float(Ph[127 + jB]);
                split_pk(preA * (1.0f - p7a), preA * p7a, ah[rr], al4[rr]);
                split_pk(preB * (1.0f - p7b), preB * p7b, ah[2 + rr], al4[2 + rr]);
            }
            #pragma unroll
            for (int np = 0; np < 2; np++) {
                const char* bp0 = LB + sl2 * 4096 + (nwarp2 * 4 + 2 * np) * 512 + lane * 16;
                const char* bp1 = bp0 + 512;
                uint4 bh0 = *(const uint4*)bp0;
                uint4 bl0 = *(const uint4*)(bp0 + 16384);
                uint4 bh1 = *(const uint4*)bp1;
                uint4 bl1 = *(const uint4*)(bp1 + 16384);
                float* a0 = acc2[4 * np + 0];
                float* a1 = acc2[4 * np + 1];
                float* a2 = acc2[4 * np + 2];
                float* a3 = acc2[4 * np + 3];
                mma_bf16(a0, ah, bh0.x, bh0.y);
                mma_bf16(a1, ah, bh0.z, bh0.w);
                mma_bf16(a2, ah, bh1.x, bh1.y);
                mma_bf16(a3, ah, bh1.z, bh1.w);
                mma_bf16(a0, ah, bl0.x, bl0.y);
                mma_bf16(a1, ah, bl0.z, bl0.w);
                mma_bf16(a2, ah, bl1.x, bl1.y);
                mma_bf16(a3, ah, bl1.z, bl1.w);
                mma_bf16(a0, al4, bh0.x, bh0.y);
                mma_bf16(a1, al4, bh0.z, bh0.w);
                mma_bf16(a2, al4, bh1.x, bh1.y);
                mma_bf16(a3, al4, bh1.z, bh1.w);
            }
        }
    }
    __syncthreads();   // all P reads done

    // ---- output bounce (coalesce) ----
    float* ob = (float*)smc;    // [64][132]
    #pragma unroll
    for (int nt = 0; nt < 8; nt++)
        #pragma unroll
        for (int cc = 0; cc < 4; cc++) {
            int row = mwarp2 * 16 + (lane >> 2) + ((cc >> 1) << 3);
            int col = nwarp2 * 64 + nt * 8 + 2 * (lane & 3) + (cc & 1);
            ob[row * 132 + col] = acc2[nt][cc];
        }
    __syncthreads();
    #pragma unroll
    for (int i = 0; i < 8; i++) {
        int e = tid + i * 256;
        int rr = e >> 5, cq = e & 31;
        *(float4*)(out + (size_t)(m0 + rr) * 128 + cq * 4) = *(const float4*)(ob + rr * 132 + cq * 4);
    }

    // ---- regularizer reduction ----
    #pragma unroll
    for (int o = 16; o; o >>= 1) racc += __shfl_xor_sync(0xFFFFFFFFu, racc, o);
    if (lane == 0) atomicAdd(&s_racc, racc);
    __syncthreads();
    if (tid == 0) atomicAdd(regp, s_racc * (-0.5f / 65536.0f));
}

extern "C" void kernel_launch(void* const* d_in, const int* in_sizes, int n_in,
                              void* d_out, int out_size) {
    const float* x    = (const float*)d_in[0];
    const float* W    = (const float*)d_in[1];
    const float* bsp  = (const float*)d_in[2];
    const float* leaf = (const float*)d_in[3];
    float* out  = (float*)d_out;
    float* regp = out + (out_size - 1);
    cudaFuncSetAttribute(tree_main, cudaFuncAttributeMaxDynamicSharedMemorySize, SMEM_DYN);
    init_reg<<<1, 1>>>(regp);
    prep_w<<<1024, 256>>>(W);
    prep_leaf<<<128, 256>>>(leaf);
    tree_main<<<1024, 256, SMEM_DYN>>>(x, bsp, out, regp);
}

// round 11
// speedup vs baseline: 1.0164x; 1.0164x over previous
#include <cuda_runtime.h>
#include <cuda_fp16.h>
#include <cuda_bf16.h>
#include <cstdint>

#define ABLK  528
#define ASZ   8448       // 16 A-blocks * 528B per variant
#define OFF_W 16896      // 2*ASZ
#define STG   49664      // OFF_W + 32768 (W tile)
#define PSTRF 260        // float elems per P row (260 mod 32 = 4, conflict-free)
#define OFF_LB 66560     // = 64*260*4 (P bytes); leaf buffers follow
#define SMEM_DYN 99328   // OFF_LB + 2*16384

static __device__ __half       g_Wh[262144];     // W fp16 single, frag-linear
static __device__ __nv_bfloat16 g_Lf_hi[32768];
static __device__ __nv_bfloat16 g_Lf_lo[32768];

__device__ __forceinline__ uint32_t smem_u32(const void* p) {
    uint32_t a;
    asm("{ .reg .u64 t; cvta.to.shared.u64 t, %1; cvt.u32.u64 %0, t; }" : "=r"(a) : "l"(p));
    return a;
}
__device__ __forceinline__ void cp16(uint32_t dst, const void* src) {
    asm volatile("cp.async.cg.shared.global [%0], [%1], 16;" :: "r"(dst), "l"(src) : "memory");
}
#define CP_COMMIT() asm volatile("cp.async.commit_group;" ::: "memory")
#define CP_WAIT0()  asm volatile("cp.async.wait_group 0;" ::: "memory")

__device__ __forceinline__ void mma_f16(float* c, const uint32_t* a, uint32_t b0, uint32_t b1) {
    asm volatile("mma.sync.aligned.m16n8k16.row.col.f32.f16.f16.f32 "
        "{%0,%1,%2,%3}, {%4,%5,%6,%7}, {%8,%9}, {%0,%1,%2,%3};"
        : "+f"(c[0]), "+f"(c[1]), "+f"(c[2]), "+f"(c[3])
        : "r"(a[0]), "r"(a[1]), "r"(a[2]), "r"(a[3]), "r"(b0), "r"(b1));
}
__device__ __forceinline__ void mma_bf16(float* c, const uint32_t* a, uint32_t b0, uint32_t b1) {
    asm volatile("mma.sync.aligned.m16n8k16.row.col.f32.bf16.bf16.f32 "
        "{%0,%1,%2,%3}, {%4,%5,%6,%7}, {%8,%9}, {%0,%1,%2,%3};"
        : "+f"(c[0]), "+f"(c[1]), "+f"(c[2]), "+f"(c[3])
        : "r"(a[0]), "r"(a[1]), "r"(a[2]), "r"(a[3]), "r"(b0), "r"(b1));
}
__device__ __forceinline__ uint32_t pack_h2(float a, float b) {
    __half2 t = __floats2half2_rn(a, b);
    return *reinterpret_cast<uint32_t*>(&t);
}
__device__ __forceinline__ void split_h(float v0, float v1, uint32_t& hi, uint32_t& lo) {
    __half h0 = __float2half_rn(v0), h1 = __float2half_rn(v1);
    hi = pack_h2(__half2float(h0), __half2float(h1));
    lo = pack_h2(v0 - __half2float(h0), v1 - __half2float(h1));
}
__device__ __forceinline__ uint32_t pack_bf2(float a, float b) {
    __nv_bfloat162 t = __floats2bfloat162_rn(a, b);
    return *reinterpret_cast<uint32_t*>(&t);
}
__device__ __forceinline__ void split_pk(float pe, float po, uint32_t& hi, uint32_t& lo) {
    __nv_bfloat16 he = __float2bfloat16(pe), ho = __float2bfloat16(po);
    hi = pack_bf2(__bfloat162float(he), __bfloat162float(ho));
    lo = pack_bf2(pe - __bfloat162float(he), po - __bfloat162float(ho));
}

// W[k][n] -> frag-linear fp16 single, 16 K64-chunks, paired n-tiles
__global__ void prep_w(const float* __restrict__ W) {
    int idx = blockIdx.x * 256 + threadIdx.x;
    int k = idx >> 8, n = idx & 255;
    float v = (n < 255) ? W[k * 255 + n] : 0.0f;
    int chunk = k >> 6, kin = k & 63, s = kin >> 4, kk = kin & 15;
    int nt = n >> 3, pr = nt >> 1, e = nt & 1;
    int tl = (n & 7) * 4 + ((kk >> 1) & 3), rg = kk >> 3, hf = kk & 1;
    int o = chunk * 16384 + s * 4096 + pr * 256 + tl * 8 + e * 4 + rg * 2 + hf;
    g_Wh[o] = __float2half_rn(v);
}
// leaf[k][n] (256 leaves x 128 dout) -> frag-linear bf16 hi/lo, paired n-tiles
__global__ void prep_leaf(const float* __restrict__ L) {
    int idx = blockIdx.x * 256 + threadIdx.x;
    int k = idx >> 7, n = idx & 127;
    float v = L[k * 128 + n];
    __nv_bfloat16 h = __float2bfloat16(v);
    __nv_bfloat16 l = __float2bfloat16(v - __bfloat162float(h));
    int s = k >> 4, kk = k & 15;
    int nt = n >> 3, pr = nt >> 1, e = nt & 1;
    int tl = (n & 7) * 4 + ((kk >> 1) & 3), rg = kk >> 3, hf = kk & 1;
    int o = s * 2048 + pr * 256 + tl * 8 + e * 4 + rg * 2 + hf;
    g_Lf_hi[o] = h; g_Lf_lo[o] = l;
}
__global__ void init_reg(float* regp) { *regp = 0.0f; }

__global__ void __launch_bounds__(256, 2) tree_main(
    const float* __restrict__ x, const float* __restrict__ bsp,
    float* __restrict__ out, float* __restrict__ regp)
{
    extern __shared__ char smc[];
    __shared__ float s_bias[256];
    __shared__ float s_racc;
    const uint32_t sb = smem_u32(smc);

    const int tid = threadIdx.x, lane = tid & 31, w = tid >> 5;
    const int mwarp = w & 1, nwarp = w >> 1;          // 32-row x 64-col warp tile
    const int m0 = blockIdx.x * 64;

    s_bias[tid] = (tid < 255) ? bsp[tid] : 0.0f;
    if (tid == 0) s_racc = 0.0f;

    float acc[2][8][4] = {};

    const int r = tid >> 2;             // staging row 0..63
    const int ko = (tid & 3) * 16;      // 16 consecutive k per thread

    // ---- prologue: chunk 0 (k 0..63) ----
    {
        const float* xp = x + (size_t)(m0 + r) * 1024 + ko;
        float fv[16];
        #pragma unroll
        for (int i = 0; i < 4; i++) *(float4*)(fv + 4 * i) = *(const float4*)(xp + 4 * i);
        #pragma unroll
        for (int i = 0; i < 8; i++)
            cp16(sb + OFF_W + (tid + i * 256) * 16, (const char*)g_Wh + (tid + i * 256) * 16);
        CP_COMMIT();
        #pragma unroll
        for (int q = 0; q < 8; q++) {
            int p = (tid & 3) * 8 + q;
            int s = p >> 3, pp = p & 7;
            int o = (s * 4 + (r >> 4)) * ABLK + (4 * (r & 7) + (pp & 3)) * 16
                    + (((r >> 3) & 1) + ((pp >> 2) << 1)) * 4;
            uint32_t hv, lv;
            split_h(fv[2 * q], fv[2 * q + 1], hv, lv);
            *(uint32_t*)(smc + o) = hv;
            *(uint32_t*)(smc + o + ASZ) = lv;
        }
    }

    // ---- GEMM1: 16 K64-chunks, double-buffered; x hi/lo fp16 2-pass vs W fp16 ----
    for (int c = 0; c < 16; c++) {
        const int st = c & 1, nst = st ^ 1;
        float fv[16];
        if (c < 15) {   // x prefetch before the wait
            const float* xp = x + (size_t)(m0 + r) * 1024 + (c + 1) * 64 + ko;
            #pragma unroll
            for (int i = 0; i < 4; i++) *(float4*)(fv + 4 * i) = *(const float4*)(xp + 4 * i);
        }
        CP_WAIT0();
        __syncthreads();
        if (c < 15) {
            const char* srcW = (const char*)g_Wh + (c + 1) * 32768;
            #pragma unroll
            for (int i = 0; i < 8; i++)
                cp16(sb + nst * STG + OFF_W + (tid + i * 256) * 16, srcW + (tid + i * 256) * 16);
            CP_COMMIT();
        }
        #pragma unroll
        for (int s = 0; s < 4; s++) {
            uint32_t ah[2][4], al[2][4];
            #pragma unroll
            for (int mt = 0; mt < 2; mt++) {
                const char* ap = smc + st * STG + (s * 4 + mwarp * 2 + mt) * ABLK + lane * 16;
                *(uint4*)ah[mt] = *(const uint4*)ap;
                *(uint4*)al[mt] = *(const uint4*)(ap + ASZ);
            }
            #pragma unroll
            for (int ntp = 0; ntp < 4; ntp++) {
                const char* bp = smc + st * STG + OFF_W + s * 8192 + (nwarp * 4 + ntp) * 512 + lane * 16;
                uint4 bq = *(const uint4*)bp;
                mma_f16(acc[0][2 * ntp],     ah[0], bq.x, bq.y);
                mma_f16(acc[0][2 * ntp + 1], ah[0], bq.z, bq.w);
                mma_f16(acc[1][2 * ntp],     ah[1], bq.x, bq.y);
                mma_f16(acc[1][2 * ntp + 1], ah[1], bq.z, bq.w);
                mma_f16(acc[0][2 * ntp],     al[0], bq.x, bq.y);
                mma_f16(acc[0][2 * ntp + 1], al[0], bq.z, bq.w);
                mma_f16(acc[1][2 * ntp],     al[1], bq.x, bq.y);
                mma_f16(acc[1][2 * ntp + 1], al[1], bq.z, bq.w);
            }
        }
        if (c < 15) {
            #pragma unroll
            for (int q = 0; q < 8; q++) {
                int p = (tid & 3) * 8 + q;
                int s = p >> 3, pp = p & 7;
                int o = nst * STG + (s * 4 + (r >> 4)) * ABLK + (4 * (r & 7) + (pp & 3)) * 16
                        + (((r >> 3) & 1) + ((pp >> 2) << 1)) * 4;
                uint32_t hv, lv;
                split_h(fv[2 * q], fv[2 * q + 1], hv, lv);
                *(uint32_t*)(smc + o) = hv;
                *(uint32_t*)(smc + o + ASZ) = lv;
            }
        }
    }
    __syncthreads();   // GEMM1 regions dead

    // ---- prefetch leaf piece 0, then sigmoid + reg; P -> SMEM fp32 ----
    #pragma unroll
    for (int i = 0; i < 2; i++) {
        cp16(sb + OFF_LB + (tid + i * 256) * 16, (const char*)g_Lf_hi + (tid + i * 256) * 16);
        cp16(sb + OFF_LB + 8192 + (tid + i * 256) * 16, (const char*)g_Lf_lo + (tid + i * 256) * 16);
    }
    CP_COMMIT();

    float racc = 0.0f;
    float* Pf0 = (float*)smc;
    #pragma unroll
    for (int mt = 0; mt < 2; mt++)
        #pragma unroll
        for (int nt = 0; nt < 8; nt++)
            #pragma unroll
            for (int cc = 0; cc < 4; cc++) {
                int row = mwarp * 32 + mt * 16 + (lane >> 2) + ((cc >> 1) << 3);
                int col = nwarp * 64 + nt * 8 + 2 * (lane & 3) + (cc & 1);
                if (col < 255) {
                    float lg = acc[mt][nt][cc] + s_bias[col];
                    float p = 1.0f / (1.0f + __expf(-lg));
                    Pf0[row * PSTRF + col] = p;
                    int d = 31 - __clz(col + 1);
                    racc += __uint_as_float((uint32_t)(127 - d) << 23) *
                            __logf(fmaxf(p * (1.0f - p), 1e-5f));
                }
            }

    // ---- GEMM2: tree-product A frags + leaf pieces (8 x 16KB, double-buffered) ----
    float acc2[8][4] = {};
    const int mwarp2 = w & 3, nwarp2 = w >> 2;
    const int la = lane & 3;
    #pragma unroll 1
    for (int qq = 0; qq < 8; qq++) {
        CP_WAIT0();
        __syncthreads();
        if (qq < 7) {
            uint32_t db = sb + OFF_LB + ((qq + 1) & 1) * 16384;
            const char* sh = (const char*)(g_Lf_hi + (qq + 1) * 4096);
            const char* sl = (const char*)(g_Lf_lo + (qq + 1) * 4096);
            #pragma unroll
            for (int i = 0; i < 2; i++) {
                cp16(db + (tid + i * 256) * 16, sh + (tid + i * 256) * 16);
                cp16(db + 8192 + (tid + i * 256) * 16, sl + (tid + i * 256) * 16);
            }
            CP_COMMIT();
        }
        const char* LB = smc + OFF_LB + (qq & 1) * 16384;
        #pragma unroll
        for (int sl2 = 0; sl2 < 2; sl2++) {
            int s = qq * 2 + sl2;
            int jA = 8 * s + la, jB = jA + 4;
            uint32_t ah[4], al4[4];
            #pragma unroll
            for (int rr = 0; rr < 2; rr++) {
                int row = mwarp2 * 16 + (lane >> 2) + rr * 8;
                const float* Pf = Pf0 + row * PSTRF;
                float pv, pre;
                pv = Pf[s >> 4];       pre  = ((s >> 3) & 1) ? pv : 1.0f - pv;
                pv = Pf[1 + (s >> 3)]; pre *= ((s >> 2) & 1) ? pv : 1.0f - pv;
                pv = Pf[3 + (s >> 2)]; pre *= ((s >> 1) & 1) ? pv : 1.0f - pv;
                pv = Pf[7 + (s >> 1)]; pre *= (s & 1) ? pv : 1.0f - pv;
                float p4 = Pf[15 + s];
                float preA = pre * (1.0f - p4), preB = pre * p4;
                int b5 = (la >> 1) & 1, b6 = la & 1;
                float p5a = Pf[31 + 2 * s];
                float p5b = Pf[31 + 2 * s + 1];
                preA *= b5 ? p5a : 1.0f - p5a;
                preB *= b5 ? p5b : 1.0f - p5b;
                float p6a = Pf[63 + (jA >> 1)];
                float p6b = Pf[63 + (jB >> 1)];
                preA *= b6 ? p6a : 1.0f - p6a;
                preB *= b6 ? p6b : 1.0f - p6b;
                float p7a = Pf[127 + jA];
                float p7b = Pf[127 + jB];
                split_pk(preA * (1.0f - p7a), preA * p7a, ah[rr], al4[rr]);
                split_pk(preB * (1.0f - p7b), preB * p7b, ah[2 + rr], al4[2 + rr]);
            }
            #pragma unroll
            for (int np = 0; np < 2; np++) {
                const char* bp0 = LB + sl2 * 4096 + (nwarp2 * 4 + 2 * np) * 512 + lane * 16;
                const char* bp1 = bp0 + 512;
                uint4 bh0 = *(const uint4*)bp0;
                uint4 bl0 = *(const uint4*)(bp0 + 8192);
                uint4 bh1 = *(const uint4*)bp1;
                uint4 bl1 = *(const uint4*)(bp1 + 8192);
                float* a0 = acc2[4 * np + 0];
                float* a1 = acc2[4 * np + 1];
                float* a2 = acc2[4 * np + 2];
                float* a3 = acc2[4 * np + 3];
                mma_bf16(a0, ah, bh0.x, bh0.y);
                mma_bf16(a1, ah, bh0.z, bh0.w);
                mma_bf16(a2, ah, bh1.x, bh1.y);
                mma_bf16(a3, ah, bh1.z, bh1.w);
                mma_bf16(a0, ah, bl0.x, bl0.y);
                mma_bf16(a1, ah, bl0.z, bl0.w);
                mma_bf16(a2, ah, bl1.x, bl1.y);
                mma_bf16(a3, ah, bl1.z, bl1.w);
                mma_bf16(a0, al4, bh0.x, bh0.y);
                mma_bf16(a1, al4, bh0.z, bh0.w);
                mma_bf16(a2, al4, bh1.x, bh1.y);
                mma_bf16(a3, al4, bh1.z, bh1.w);
            }
        }
    }
    __syncthreads();   // all P reads done

    // ---- output bounce (coalesce) ----
    float* ob = (float*)smc;    // [64][132]
    #pragma unroll
    for (int nt = 0; nt < 8; nt++)
        #pragma unroll
        for (int cc = 0; cc < 4; cc++) {
            int row = mwarp2 * 16 + (lane >> 2) + ((cc >> 1) << 3);
            int col = nwarp2 * 64 + nt * 8 + 2 * (lane & 3) + (cc & 1);
            ob[row * 132 + col] = acc2[nt][cc];
        }
    __syncthreads();
    #pragma unroll
    for (int i = 0; i < 8; i++) {
        int e = tid + i * 256;
        int rr = e >> 5, cq = e & 31;
        *(float4*)(out + (size_t)(m0 + rr) * 128 + cq * 4) = *(const float4*)(ob + rr * 132 + cq * 4);
    }

    // ---- regularizer reduction ----
    #pragma unroll
    for (int o = 16; o; o >>= 1) racc += __shfl_xor_sync(0xFFFFFFFFu, racc, o);
    if (lane == 0) atomicAdd(&s_racc, racc);
    __syncthreads();
    if (tid == 0) atomicAdd(regp, s_racc * (-0.5f / 65536.0f));
}

extern "C" void kernel_launch(void* const* d_in, const int* in_sizes, int n_in,
                              void* d_out, int out_size) {
    const float* x    = (const float*)d_in[0];
    const float* W    = (const float*)d_in[1];
    const float* bsp  = (const float*)d_in[2];
    const float* leaf = (const float*)d_in[3];
    float* out  = (float*)d_out;
    float* regp = out + (out_size - 1);
    cudaFuncSetAttribute(tree_main, cudaFuncAttributeMaxDynamicSharedMemorySize, SMEM_DYN);
    init_reg<<<1, 1>>>(regp);
    prep_w<<<1024, 256>>>(W);
    prep_leaf<<<128, 256>>>(leaf);
    tree_main<<<1024, 256, SMEM_DYN>>>(x, bsp, out, regp);
}

// round 14
// speedup vs baseline: 1.3026x; 1.2816x over previous
#include <cuda_runtime.h>
#include <cuda_fp16.h>
#include <cuda_bf16.h>
#include <cstdint>

#define OFF_WX 16384     // x fp32 stage = 16KB, then W 32KB
#define STG    49152
#define PSTRF  260       // float elems per P row (conflict-free)
#define OFF_LB 66560     // = 64*260*4 (P bytes); leaf buffers follow
#define SMEM_DYN 99328   // OFF_LB + 2*16384

static __device__ __half        g_Wh[262144];    // W fp16, frag-linear, k-permuted
static __device__ __nv_bfloat16 g_Lf_hi[32768];
static __device__ __nv_bfloat16 g_Lf_lo[32768];

__device__ __forceinline__ uint32_t smem_u32(const void* p) {
    uint32_t a;
    asm("{ .reg .u64 t; cvta.to.shared.u64 t, %1; cvt.u32.u64 %0, t; }" : "=r"(a) : "l"(p));
    return a;
}
__device__ __forceinline__ void cp16(uint32_t dst, const void* src) {
    asm volatile("cp.async.cg.shared.global [%0], [%1], 16;" :: "r"(dst), "l"(src) : "memory");
}
#define CP_COMMIT() asm volatile("cp.async.commit_group;" ::: "memory")
#define CP_WAIT0()  asm volatile("cp.async.wait_group 0;" ::: "memory")

__device__ __forceinline__ void mma_f16(float* c, const uint32_t* a, uint32_t b0, uint32_t b1) {
    asm volatile("mma.sync.aligned.m16n8k16.row.col.f32.f16.f16.f32 "
        "{%0,%1,%2,%3}, {%4,%5,%6,%7}, {%8,%9}, {%0,%1,%2,%3};"
        : "+f"(c[0]), "+f"(c[1]), "+f"(c[2]), "+f"(c[3])
        : "r"(a[0]), "r"(a[1]), "r"(a[2]), "r"(a[3]), "r"(b0), "r"(b1));
}
__device__ __forceinline__ void mma_bf16(float* c, const uint32_t* a, uint32_t b0, uint32_t b1) {
    asm volatile("mma.sync.aligned.m16n8k16.row.col.f32.bf16.bf16.f32 "
        "{%0,%1,%2,%3}, {%4,%5,%6,%7}, {%8,%9}, {%0,%1,%2,%3};"
        : "+f"(c[0]), "+f"(c[1]), "+f"(c[2]), "+f"(c[3])
        : "r"(a[0]), "r"(a[1]), "r"(a[2]), "r"(a[3]), "r"(b0), "r"(b1));
}
__device__ __forceinline__ uint32_t pack_h2(float a, float b) {
    __half2 t = __floats2half2_rn(a, b);
    return *reinterpret_cast<uint32_t*>(&t);
}
__device__ __forceinline__ void split_h(float v0, float v1, uint32_t& hi, uint32_t& lo) {
    __half h0 = __float2half_rn(v0), h1 = __float2half_rn(v1);
    hi = pack_h2(__half2float(h0), __half2float(h1));
    lo = pack_h2(v0 - __half2float(h0), v1 - __half2float(h1));
}
__device__ __forceinline__ uint32_t pack_bf2(float a, float b) {
    __nv_bfloat162 t = __floats2bfloat162_rn(a, b);
    return *reinterpret_cast<uint32_t*>(&t);
}
__device__ __forceinline__ void split_pk(float pe, float po, uint32_t& hi, uint32_t& lo) {
    __nv_bfloat16 he = __float2bfloat16(pe), ho = __float2bfloat16(po);
    hi = pack_bf2(__bfloat162float(he), __bfloat162float(ho));
    lo = pack_bf2(pe - __bfloat162float(he), po - __bfloat162float(ho));
}

// W[k][n] -> frag-linear fp16, 16 K64-chunks, paired n-tiles, k-slot permuted:
// mma slot (tig,rg,hf) <-> global k offset 4*tig + 2*rg + hf
__global__ void prep_w(const float* __restrict__ W) {
    int idx = blockIdx.x * 256 + threadIdx.x;
    int k = idx >> 8, n = idx & 255;
    float v = (n < 255) ? W[k * 255 + n] : 0.0f;
    int chunk = k >> 6, kin = k & 63, s = kin >> 4, kk = kin & 15;
    int tig = kk >> 2, rg = (kk >> 1) & 1, hf = kk & 1;
    int nt = n >> 3, pr = nt >> 1, e = nt & 1;
    int tl = (n & 7) * 4 + tig;
    int o = chunk * 16384 + s * 4096 + pr * 256 + tl * 8 + e * 4 + rg * 2 + hf;
    g_Wh[o] = __float2half_rn(v);
}
// leaf[k][n] (256 leaves x 128 dout) -> frag-linear bf16 hi/lo, paired n-tiles
__global__ void prep_leaf(const float* __restrict__ L) {
    int idx = blockIdx.x * 256 + threadIdx.x;
    int k = idx >> 7, n = idx & 127;
    float v = L[k * 128 + n];
    __nv_bfloat16 h = __float2bfloat16(v);
    __nv_bfloat16 l = __float2bfloat16(v - __bfloat162float(h));
    int s = k >> 4, kk = k & 15;
    int nt = n >> 3, pr = nt >> 1, e = nt & 1;
    int tl = (n & 7) * 4 + ((kk >> 1) & 3), rg = kk >> 3, hf = kk & 1;
    int o = s * 2048 + pr * 256 + tl * 8 + e * 4 + rg * 2 + hf;
    g_Lf_hi[o] = h; g_Lf_lo[o] = l;
}
__global__ void init_reg(float* regp) { *regp = 0.0f; }

__global__ void __launch_bounds__(256, 2) tree_main(
    const float* __restrict__ x, const float* __restrict__ bsp,
    float* __restrict__ out, float* __restrict__ regp)
{
    extern __shared__ char smc[];
    __shared__ float s_bias[256];
    __shared__ float s_racc;
    const uint32_t sb = smem_u32(smc);

    const int tid = threadIdx.x, lane = tid & 31, w = tid >> 5;
    const int mwarp = w & 1, nwarp = w >> 1;          // 32-row x 64-col warp tile
    const int m0 = blockIdx.x * 64;

    s_bias[tid] = (tid < 255) ? bsp[tid] : 0.0f;
    if (tid == 0) s_racc = 0.0f;

    float acc[2][8][4] = {};

    // ---- prologue: chunk 0 (x fp32 + W fp16) ----
    {
        #pragma unroll
        for (int i = 0; i < 4; i++) {
            int e = tid + i * 256, row = e >> 4, cc = e & 15;
            cp16(sb + row * 256 + ((cc ^ ((row & 1) << 2)) << 4),
                 x + (size_t)(m0 + row) * 1024 + cc * 4);
        }
        #pragma unroll
        for (int i = 0; i < 8; i++)
            cp16(sb + OFF_WX + (tid + i * 256) * 16, (const char*)g_Wh + (tid + i * 256) * 16);
        CP_COMMIT();
    }

    // ---- GEMM1: 16 K64-chunks, double-buffered; A frags direct from fp32 smem ----
    for (int c = 0; c < 16; c++) {
        const int st = c & 1, nst = st ^ 1;
        CP_WAIT0();
        __syncthreads();
        if (c < 15) {
            #pragma unroll
            for (int i = 0; i < 4; i++) {
                int e = tid + i * 256, row = e >> 4, cc = e & 15;
                cp16(sb + nst * STG + row * 256 + ((cc ^ ((row & 1) << 2)) << 4),
                     x + (size_t)(m0 + row) * 1024 + (c + 1) * 64 + cc * 4);
            }
            const char* srcW = (const char*)g_Wh + (c + 1) * 32768;
            #pragma unroll
            for (int i = 0; i < 8; i++)
                cp16(sb + nst * STG + OFF_WX + (tid + i * 256) * 16, srcW + (tid + i * 256) * 16);
            CP_COMMIT();
        }
        #pragma unroll
        for (int s = 0; s < 4; s++) {
            uint32_t ah[2][4], al[2][4];
            #pragma unroll
            for (int mt = 0; mt < 2; mt++) {
                int r0 = mwarp * 32 + mt * 16 + (lane >> 2);
                int c4 = s * 4 + (lane & 3);
                int sw = (c4 ^ ((r0 & 1) << 2)) << 4;     // r0+8 has same parity
                const char* xs = smc + st * STG;
                float4 x0 = *(const float4*)(xs + r0 * 256 + sw);
                float4 x1 = *(const float4*)(xs + (r0 + 8) * 256 + sw);
                split_h(x0.x, x0.y, ah[mt][0], al[mt][0]);
                split_h(x1.x, x1.y, ah[mt][1], al[mt][1]);
                split_h(x0.z, x0.w, ah[mt][2], al[mt][2]);
                split_h(x1.z, x1.w, ah[mt][3], al[mt][3]);
            }
            #pragma unroll
            for (int ntp = 0; ntp < 4; ntp++) {
                const char* bp = smc + st * STG + OFF_WX + s * 8192 + (nwarp * 4 + ntp) * 512 + lane * 16;
                uint4 bq = *(const uint4*)bp;
                mma_f16(acc[0][2 * ntp],     ah[0], bq.x, bq.y);
                mma_f16(acc[0][2 * ntp + 1], ah[0], bq.z, bq.w);
                mma_f16(acc[1][2 * ntp],     ah[1], bq.x, bq.y);
                mma_f16(acc[1][2 * ntp + 1], ah[1], bq.z, bq.w);
                mma_f16(acc[0][2 * ntp],     al[0], bq.x, bq.y);
                mma_f16(acc[0][2 * ntp + 1], al[0], bq.z, bq.w);
                mma_f16(acc[1][2 * ntp],     al[1], bq.x, bq.y);
                mma_f16(acc[1][2 * ntp + 1], al[1], bq.z, bq.w);
            }
        }
    }
    __syncthreads();   // GEMM1 regions dead

    // ---- prefetch leaf piece 0, then sigmoid + reg; P -> SMEM fp32 ----
    #pragma unroll
    for (int i = 0; i < 2; i++) {
        cp16(sb + OFF_LB + (tid + i * 256) * 16, (const char*)g_Lf_hi + (tid + i * 256) * 16);
        cp16(sb + OFF_LB + 8192 + (tid + i * 256) * 16, (const char*)g_Lf_lo + (tid + i * 256) * 16);
    }
    CP_COMMIT();

    float racc = 0.0f;
    float* Pf0 = (float*)smc;
    #pragma unroll
    for (int mt = 0; mt < 2; mt++)
        #pragma unroll
        for (int nt = 0; nt < 8; nt++)
            #pragma unroll
            for (int cc = 0; cc < 4; cc++) {
                int row = mwarp * 32 + mt * 16 + (lane >> 2) + ((cc >> 1) << 3);
                int col = nwarp * 64 + nt * 8 + 2 * (lane & 3) + (cc & 1);
                if (col < 255) {
                    float lg = acc[mt][nt][cc] + s_bias[col];
                    float p = 1.0f / (1.0f + __expf(-lg));
                    Pf0[row * PSTRF + col] = p;
                    int d = 31 - __clz(col + 1);
                    racc += __uint_as_float((uint32_t)(127 - d) << 23) *
                            __logf(fmaxf(p * (1.0f - p), 1e-5f));
                }
            }

    // ---- GEMM2: tree-product A frags + leaf pieces (8 x 16KB, double-buffered) ----
    float acc2[8][4] = {};
    const int mwarp2 = w & 3, nwarp2 = w >> 2;
    const int la = lane & 3;
    #pragma unroll 1
    for (int qq = 0; qq < 8; qq++) {
        CP_WAIT0();
        __syncthreads();
        if (qq < 7) {
            uint32_t db = sb + OFF_LB + ((qq + 1) & 1) * 16384;
            const char* sh = (const char*)(g_Lf_hi + (qq + 1) * 4096);
            const char* sl = (const char*)(g_Lf_lo + (qq + 1) * 4096);
            #pragma unroll
            for (int i = 0; i < 2; i++) {
                cp16(db + (tid + i * 256) * 16, sh + (tid + i * 256) * 16);
                cp16(db + 8192 + (tid + i * 256) * 16, sl + (tid + i * 256) * 16);
            }
            CP_COMMIT();
        }
        const char* LB = smc + OFF_LB + (qq & 1) * 16384;
        #pragma unroll
        for (int sl2 = 0; sl2 < 2; sl2++) {
            int s = qq * 2 + sl2;
            int jA = 8 * s + la, jB = jA + 4;
            uint32_t ah[4], al4[4];
            #pragma unroll
            for (int rr = 0; rr < 2; rr++) {
                int row = mwarp2 * 16 + (lane >> 2) + rr * 8;
                const float* Pf = Pf0 + row * PSTRF;
                float pv, pre;
                pv = Pf[s >> 4];       pre  = ((s >> 3) & 1) ? pv : 1.0f - pv;
                pv = Pf[1 + (s >> 3)]; pre *= ((s >> 2) & 1) ? pv : 1.0f - pv;
                pv = Pf[3 + (s >> 2)]; pre *= ((s >> 1) & 1) ? pv : 1.0f - pv;
                pv = Pf[7 + (s >> 1)]; pre *= (s & 1) ? pv : 1.0f - pv;
                float p4 = Pf[15 + s];
                float preA = pre * (1.0f - p4), preB = pre * p4;
                int b5 = (la >> 1) & 1, b6 = la & 1;
                float p5a = Pf[31 + 2 * s];
                float p5b = Pf[31 + 2 * s + 1];
                preA *= b5 ? p5a : 1.0f - p5a;
                preB *= b5 ? p5b : 1.0f - p5b;
                float p6a = Pf[63 + (jA >> 1)];
                float p6b = Pf[63 + (jB >> 1)];
                preA *= b6 ? p6a : 1.0f - p6a;
                preB *= b6 ? p6b : 1.0f - p6b;
                float p7a = Pf[127 + jA];
                float p7b = Pf[127 + jB];
                split_pk(preA * (1.0f - p7a), preA * p7a, ah[rr], al4[rr]);
                split_pk(preB * (1.0f - p7b), preB * p7b, ah[2 + rr], al4[2 + rr]);
            }
            #pragma unroll
            for (int np = 0; np < 2; np++) {
                const char* bp0 = LB + sl2 * 4096 + (nwarp2 * 4 + 2 * np) * 512 + lane * 16;
                const char* bp1 = bp0 + 512;
                uint4 bh0 = *(const uint4*)bp0;
                uint4 bl0 = *(const uint4*)(bp0 + 8192);
                uint4 bh1 = *(const uint4*)bp1;
                uint4 bl1 = *(const uint4*)(bp1 + 8192);
                float* a0 = acc2[4 * np + 0];
                float* a1 = acc2[4 * np + 1];
                float* a2 = acc2[4 * np + 2];
                float* a3 = acc2[4 * np + 3];
                mma_bf16(a0, ah, bh0.x, bh0.y);
                mma_bf16(a1, ah, bh0.z, bh0.w);
                mma_bf16(a2, ah, bh1.x, bh1.y);
                mma_bf16(a3, ah, bh1.z, bh1.w);
                mma_bf16(a0, ah, bl0.x, bl0.y);
                mma_bf16(a1, ah, bl0.z, bl0.w);
                mma_bf16(a2, ah, bl1.x, bl1.y);
                mma_bf16(a3, ah, bl1.z, bl1.w);
                mma_bf16(a0, al4, bh0.x, bh0.y);
                mma_bf16(a1, al4, bh0.z, bh0.w);
                mma_bf16(a2, al4, bh1.x, bh1.y);
                mma_bf16(a3, al4, bh1.z, bh1.w);
            }
        }
    }
    __syncthreads();   // all P reads done

    // ---- output bounce (coalesce) ----
    float* ob = (float*)smc;    // [64][132]
    #pragma unroll
    for (int nt = 0; nt < 8; nt++)
        #pragma unroll
        for (int cc = 0; cc < 4; cc++) {
            int row = mwarp2 * 16 + (lane >> 2) + ((cc >> 1) << 3);
            int col = nwarp2 * 64 + nt * 8 + 2 * (lane & 3) + (cc & 1);
            ob[row * 132 + col] = acc2[nt][cc];
        }
    __syncthreads();
    #pragma unroll
    for (int i = 0; i < 8; i++) {
        int e = tid + i * 256;
        int rr = e >> 5, cq = e & 31;
        *(float4*)(out + (size_t)(m0 + rr) * 128 + cq * 4) = *(const float4*)(ob + rr * 132 + cq * 4);
    }

    // ---- regularizer reduction ----
    #pragma unroll
    for (int o = 16; o; o >>= 1) racc += __shfl_xor_sync(0xFFFFFFFFu, racc, o);
    if (lane == 0) atomicAdd(&s_racc, racc);
    __syncthreads();
    if (tid == 0) atomicAdd(regp, s_racc * (-0.5f / 65536.0f));
}

extern "C" void kernel_launch(void* const* d_in, const int* in_sizes, int n_in,
                              void* d_out, int out_size) {
    const float* x    = (const float*)d_in[0];
    const float* W    = (const float*)d_in[1];
    const float* bsp  = (const float*)d_in[2];
    const float* leaf = (const float*)d_in[3];
    float* out  = (float*)d_out;
    float* regp = out + (out_size - 1);
    cudaFuncSetAttribute(tree_main, cudaFuncAttributeMaxDynamicSharedMemorySize, SMEM_DYN);
    init_reg<<<1, 1>>>(regp);
    prep_w<<<1024, 256>>>(W);
    prep_leaf<<<128, 256>>>(leaf);
    tree_main<<<1024, 256, SMEM_DYN>>>(x, bsp, out, regp);
}

// round 15
// speedup vs baseline: 1.8791x; 1.4426x over previous
#include <cuda_runtime.h>
#include <cuda_fp16.h>
#include <cuda_bf16.h>
#include <cstdint>

#define OFF_WX 16384     // x fp32 stage = 16KB, then W 32KB
#define STG    49152
#define PSTRF  260       // float elems per P row (conflict-free)
#define OFF_LB 66560     // = 64*260*4 (P bytes); leaf buffers follow
#define SMEM_DYN 99328   // OFF_LB + 2*16384

static __device__ __half g_Wh[262144];   // W fp16, frag-linear, k-permuted
static __device__ __half g_Lhf[32768];   // leaf fp16, frag-linear

__device__ __forceinline__ uint32_t smem_u32(const void* p) {
    uint32_t a;
    asm("{ .reg .u64 t; cvta.to.shared.u64 t, %1; cvt.u32.u64 %0, t; }" : "=r"(a) : "l"(p));
    return a;
}
__device__ __forceinline__ void cp16(uint32_t dst, const void* src) {
    asm volatile("cp.async.cg.shared.global [%0], [%1], 16;" :: "r"(dst), "l"(src) : "memory");
}
#define CP_COMMIT() asm volatile("cp.async.commit_group;" ::: "memory")
#define CP_WAIT0()  asm volatile("cp.async.wait_group 0;" ::: "memory")

__device__ __forceinline__ void mma_f16(float* c, const uint32_t* a, uint32_t b0, uint32_t b1) {
    asm volatile("mma.sync.aligned.m16n8k16.row.col.f32.f16.f16.f32 "
        "{%0,%1,%2,%3}, {%4,%5,%6,%7}, {%8,%9}, {%0,%1,%2,%3};"
        : "+f"(c[0]), "+f"(c[1]), "+f"(c[2]), "+f"(c[3])
        : "r"(a[0]), "r"(a[1]), "r"(a[2]), "r"(a[3]), "r"(b0), "r"(b1));
}
__device__ __forceinline__ uint32_t pack_h2(float a, float b) {
    __half2 t = __floats2half2_rn(a, b);
    return *reinterpret_cast<uint32_t*>(&t);
}
__device__ __forceinline__ void split_h(float v0, float v1, uint32_t& hi, uint32_t& lo) {
    __half h0 = __float2half_rn(v0), h1 = __float2half_rn(v1);
    hi = pack_h2(__half2float(h0), __half2float(h1));
    lo = pack_h2(v0 - __half2float(h0), v1 - __half2float(h1));
}

// W[k][n] -> frag-linear fp16, 16 K64-chunks, paired n-tiles, k-slot permuted
__global__ void prep_w(const float* __restrict__ W) {
    int idx = blockIdx.x * 256 + threadIdx.x;
    int k = idx >> 8, n = idx & 255;
    float v = (n < 255) ? W[k * 255 + n] : 0.0f;
    int chunk = k >> 6, kin = k & 63, s = kin >> 4, kk = kin & 15;
    int tig = kk >> 2, rg = (kk >> 1) & 1, hf = kk & 1;
    int nt = n >> 3, pr = nt >> 1, e = nt & 1;
    int tl = (n & 7) * 4 + tig;
    int o = chunk * 16384 + s * 4096 + pr * 256 + tl * 8 + e * 4 + rg * 2 + hf;
    g_Wh[o] = __float2half_rn(v);
}
// leaf[k][n] (256 leaves x 128 dout) -> frag-linear fp16 single, paired n-tiles
__global__ void prep_leaf(const float* __restrict__ L) {
    int idx = blockIdx.x * 256 + threadIdx.x;
    int k = idx >> 7, n = idx & 127;
    float v = L[k * 128 + n];
    int s = k >> 4, kk = k & 15;
    int nt = n >> 3, pr = nt >> 1, e = nt & 1;
    int tl = (n & 7) * 4 + ((kk >> 1) & 3), rg = kk >> 3, hf = kk & 1;
    int o = s * 2048 + pr * 256 + tl * 8 + e * 4 + rg * 2 + hf;
    g_Lhf[o] = __float2half_rn(v);
}
__global__ void init_reg(float* regp) { *regp = 0.0f; }

__global__ void __launch_bounds__(256, 2) tree_main(
    const float* __restrict__ x, const float* __restrict__ bsp,
    float* __restrict__ out, float* __restrict__ regp)
{
    extern __shared__ char smc[];
    __shared__ float s_bias[256];
    __shared__ float s_racc;
    const uint32_t sb = smem_u32(smc);

    const int tid = threadIdx.x, lane = tid & 31, w = tid >> 5;
    const int mwarp = w & 1, nwarp = w >> 1;          // 32-row x 64-col warp tile
    const int m0 = blockIdx.x * 64;

    s_bias[tid] = (tid < 255) ? bsp[tid] : 0.0f;
    if (tid == 0) s_racc = 0.0f;

    float acc[2][8][4] = {};

    // ---- prologue: chunk 0 (x fp32 + W fp16) ----
    {
        #pragma unroll
        for (int i = 0; i < 4; i++) {
            int e = tid + i * 256, row = e >> 4, cc = e & 15;
            cp16(sb + row * 256 + ((cc ^ ((row & 1) << 2)) << 4),
                 x + (size_t)(m0 + row) * 1024 + cc * 4);
        }
        #pragma unroll
        for (int i = 0; i < 8; i++)
            cp16(sb + OFF_WX + (tid + i * 256) * 16, (const char*)g_Wh + (tid + i * 256) * 16);
        CP_COMMIT();
    }

    // ---- GEMM1: 16 K64-chunks, double-buffered; 1-pass fp16 ----
    for (int c = 0; c < 16; c++) {
        const int st = c & 1, nst = st ^ 1;
        CP_WAIT0();
        __syncthreads();
        if (c < 15) {
            #pragma unroll
            for (int i = 0; i < 4; i++) {
                int e = tid + i * 256, row = e >> 4, cc = e & 15;
                cp16(sb + nst * STG + row * 256 + ((cc ^ ((row & 1) << 2)) << 4),
                     x + (size_t)(m0 + row) * 1024 + (c + 1) * 64 + cc * 4);
            }
            const char* srcW = (const char*)g_Wh + (c + 1) * 32768;
            #pragma unroll
            for (int i = 0; i < 8; i++)
                cp16(sb + nst * STG + OFF_WX + (tid + i * 256) * 16, srcW + (tid + i * 256) * 16);
            CP_COMMIT();
        }
        #pragma unroll
        for (int s = 0; s < 4; s++) {
            uint32_t ah[2][4];
            #pragma unroll
            for (int mt = 0; mt < 2; mt++) {
                int r0 = mwarp * 32 + mt * 16 + (lane >> 2);
                int c4 = s * 4 + (lane & 3);
                int sw = (c4 ^ ((r0 & 1) << 2)) << 4;     // r0+8 has same parity
                const char* xs = smc + st * STG;
                float4 x0 = *(const float4*)(xs + r0 * 256 + sw);
                float4 x1 = *(const float4*)(xs + (r0 + 8) * 256 + sw);
                ah[mt][0] = pack_h2(x0.x, x0.y);
                ah[mt][1] = pack_h2(x1.x, x1.y);
                ah[mt][2] = pack_h2(x0.z, x0.w);
                ah[mt][3] = pack_h2(x1.z, x1.w);
            }
            #pragma unroll
            for (int ntp = 0; ntp < 4; ntp++) {
                const char* bp = smc + st * STG + OFF_WX + s * 8192 + (nwarp * 4 + ntp) * 512 + lane * 16;
                uint4 bq = *(const uint4*)bp;
                mma_f16(acc[0][2 * ntp],     ah[0], bq.x, bq.y);
                mma_f16(acc[0][2 * ntp + 1], ah[0], bq.z, bq.w);
                mma_f16(acc[1][2 * ntp],     ah[1], bq.x, bq.y);
                mma_f16(acc[1][2 * ntp + 1], ah[1], bq.z, bq.w);
            }
        }
    }
    __syncthreads();   // GEMM1 regions dead

    // ---- prefetch leaf quarter 0, then sigmoid + reg; P -> SMEM fp32 ----
    #pragma unroll
    for (int i = 0; i < 4; i++)
        cp16(sb + OFF_LB + (tid + i * 256) * 16, (const char*)g_Lhf + (tid + i * 256) * 16);
    CP_COMMIT();

    float racc = 0.0f;
    float* Pf0 = (float*)smc;
    #pragma unroll
    for (int mt = 0; mt < 2; mt++)
        #pragma unroll
        for (int nt = 0; nt < 8; nt++)
            #pragma unroll
            for (int cc = 0; cc < 4; cc++) {
                int row = mwarp * 32 + mt * 16 + (lane >> 2) + ((cc >> 1) << 3);
                int col = nwarp * 64 + nt * 8 + 2 * (lane & 3) + (cc & 1);
                if (col < 255) {
                    float lg = acc[mt][nt][cc] + s_bias[col];
                    float p = 1.0f / (1.0f + __expf(-lg));
                    Pf0[row * PSTRF + col] = p;
                    int d = 31 - __clz(col + 1);
                    racc += __uint_as_float((uint32_t)(127 - d) << 23) *
                            __logf(fmaxf(p * (1.0f - p), 1e-5f));
                }
            }

    // ---- GEMM2: probs fp16 hi/lo (2-pass) x leaf fp16; 4 x 16KB quarters ----
    float acc2[8][4] = {};
    const int mwarp2 = w & 3, nwarp2 = w >> 2;
    const int la = lane & 3;
    #pragma unroll 1
    for (int qq = 0; qq < 4; qq++) {
        CP_WAIT0();
        __syncthreads();
        if (qq < 3) {
            uint32_t db = sb + OFF_LB + ((qq + 1) & 1) * 16384;
            const char* sh = (const char*)(g_Lhf + (qq + 1) * 8192);
            #pragma unroll
            for (int i = 0; i < 4; i++)
                cp16(db + (tid + i * 256) * 16, sh + (tid + i * 256) * 16);
            CP_COMMIT();
        }
        const char* LB = smc + OFF_LB + (qq & 1) * 16384;
        #pragma unroll
        for (int sl2 = 0; sl2 < 4; sl2++) {
            int s = qq * 4 + sl2;
            int jA = 8 * s + la, jB = jA + 4;
            uint32_t ah[4], al4[4];
            #pragma unroll
            for (int rr = 0; rr < 2; rr++) {
                int row = mwarp2 * 16 + (lane >> 2) + rr * 8;
                const float* Pf = Pf0 + row * PSTRF;
                float pv, pre;
                pv = Pf[s >> 4];       pre  = ((s >> 3) & 1) ? pv : 1.0f - pv;
                pv = Pf[1 + (s >> 3)]; pre *= ((s >> 2) & 1) ? pv : 1.0f - pv;
                pv = Pf[3 + (s >> 2)]; pre *= ((s >> 1) & 1) ? pv : 1.0f - pv;
                pv = Pf[7 + (s >> 1)]; pre *= (s & 1) ? pv : 1.0f - pv;
                float p4 = Pf[15 + s];
                float preA = pre * (1.0f - p4), preB = pre * p4;
                int b5 = (la >> 1) & 1, b6 = la & 1;
                float p5a = Pf[31 + 2 * s];
                float p5b = Pf[31 + 2 * s + 1];
                preA *= b5 ? p5a : 1.0f - p5a;
                preB *= b5 ? p5b : 1.0f - p5b;
                float p6a = Pf[63 + (jA >> 1)];
                float p6b = Pf[63 + (jB >> 1)];
                preA *= b6 ? p6a : 1.0f - p6a;
                preB *= b6 ? p6b : 1.0f - p6b;
                float p7a = Pf[127 + jA];
                float p7b = Pf[127 + jB];
                split_h(preA * (1.0f - p7a), preA * p7a, ah[rr], al4[rr]);
                split_h(preB * (1.0f - p7b), preB * p7b, ah[2 + rr], al4[2 + rr]);
            }
            #pragma unroll
            for (int np = 0; np < 2; np++) {
                const char* bp0 = LB + sl2 * 4096 + (nwarp2 * 4 + 2 * np) * 512 + lane * 16;
                uint4 bh0 = *(const uint4*)bp0;
                uint4 bh1 = *(const uint4*)(bp0 + 512);
                float* a0 = acc2[4 * np + 0];
                float* a1 = acc2[4 * np + 1];
                float* a2 = acc2[4 * np + 2];
                float* a3 = acc2[4 * np + 3];
                mma_f16(a0, ah, bh0.x, bh0.y);
                mma_f16(a1, ah, bh0.z, bh0.w);
                mma_f16(a2, ah, bh1.x, bh1.y);
                mma_f16(a3, ah, bh1.z, bh1.w);
                mma_f16(a0, al4, bh0.x, bh0.y);
                mma_f16(a1, al4, bh0.z, bh0.w);
                mma_f16(a2, al4, bh1.x, bh1.y);
                mma_f16(a3, al4, bh1.z, bh1.w);
            }
        }
    }
    __syncthreads();   // all P reads done

    // ---- output bounce (coalesce) ----
    float* ob = (float*)smc;    // [64][132]
    #pragma unroll
    for (int nt = 0; nt < 8; nt++)
        #pragma unroll
        for (int cc = 0; cc < 4; cc++) {
            int row = mwarp2 * 16 + (lane >> 2) + ((cc >> 1) << 3);
            int col = nwarp2 * 64 + nt * 8 + 2 * (lane & 3) + (cc & 1);
            ob[row * 132 + col] = acc2[nt][cc];
        }
    __syncthreads();
    #pragma unroll
    for (int i = 0; i < 8; i++) {
        int e = tid + i * 256;
        int rr = e >> 5, cq = e & 31;
        *(float4*)(out + (size_t)(m0 + rr) * 128 + cq * 4) = *(const float4*)(ob + rr * 132 + cq * 4);
    }

    // ---- regularizer reduction ----
    #pragma unroll
    for (int o = 16; o; o >>= 1) racc += __shfl_xor_sync(0xFFFFFFFFu, racc, o);
    if (lane == 0) atomicAdd(&s_racc, racc);
    __syncthreads();
    if (tid == 0) atomicAdd(regp, s_racc * (-0.5f / 65536.0f));
}

extern "C" void kernel_launch(void* const* d_in, const int* in_sizes, int n_in,
                              void* d_out, int out_size) {
    const float* x    = (const float*)d_in[0];
    const float* W    = (const float*)d_in[1];
    const float* bsp  = (const float*)d_in[2];
    const float* leaf = (const float*)d_in[3];
    float* out  = (float*)d_out;
    float* regp = out + (out_size - 1);
    cudaFuncSetAttribute(tree_main, cudaFuncAttributeMaxDynamicSharedMemorySize, SMEM_DYN);
    init_reg<<<1, 1>>>(regp);
    prep_w<<<1024, 256>>>(W);
    prep_leaf<<<128, 256>>>(leaf);
    tree_main<<<1024, 256, SMEM_DYN>>>(x, bsp, out, regp);
}

// round 16
// speedup vs baseline: 1.9440x; 1.0345x over previous
#include <cuda_runtime.h>
#include <cuda_fp16.h>
#include <cuda_bf16.h>
#include <cstdint>

#define OFF_W  8192      // A fp16 frag stage = 8KB, then W 32KB
#define STG    40960
#define PSTRF  260       // float elems per P row (conflict-free)
#define OFF_LB 66560     // = 64*260*4 (P bytes); leaf buffers follow
#define SMEM_DYN 99328   // OFF_LB + 2*16384

static __device__ __half g_Wh[262144];   // W fp16, frag-linear, k-permuted
static __device__ __half g_Lhf[32768];   // leaf fp16, frag-linear

__device__ __forceinline__ uint32_t smem_u32(const void* p) {
    uint32_t a;
    asm("{ .reg .u64 t; cvta.to.shared.u64 t, %1; cvt.u32.u64 %0, t; }" : "=r"(a) : "l"(p));
    return a;
}
__device__ __forceinline__ void cp16(uint32_t dst, const void* src) {
    asm volatile("cp.async.cg.shared.global [%0], [%1], 16;" :: "r"(dst), "l"(src) : "memory");
}
#define CP_COMMIT() asm volatile("cp.async.commit_group;" ::: "memory")
#define CP_WAIT0()  asm volatile("cp.async.wait_group 0;" ::: "memory")

__device__ __forceinline__ void mma_f16(float* c, const uint32_t* a, uint32_t b0, uint32_t b1) {
    asm volatile("mma.sync.aligned.m16n8k16.row.col.f32.f16.f16.f32 "
        "{%0,%1,%2,%3}, {%4,%5,%6,%7}, {%8,%9}, {%0,%1,%2,%3};"
        : "+f"(c[0]), "+f"(c[1]), "+f"(c[2]), "+f"(c[3])
        : "r"(a[0]), "r"(a[1]), "r"(a[2]), "r"(a[3]), "r"(b0), "r"(b1));
}
__device__ __forceinline__ uint32_t pack_h2(float a, float b) {
    __half2 t = __floats2half2_rn(a, b);
    return *reinterpret_cast<uint32_t*>(&t);
}
__device__ __forceinline__ void split_h(float v0, float v1, uint32_t& hi, uint32_t& lo) {
    __half h0 = __float2half_rn(v0), h1 = __float2half_rn(v1);
    hi = pack_h2(__half2float(h0), __half2float(h1));
    lo = pack_h2(v0 - __half2float(h0), v1 - __half2float(h1));
}

// W[k][n] -> frag-linear fp16, 16 K64-chunks, paired n-tiles, k-slot permuted
__global__ void prep_w(const float* __restrict__ W) {
    int idx = blockIdx.x * 256 + threadIdx.x;
    int k = idx >> 8, n = idx & 255;
    float v = (n < 255) ? W[k * 255 + n] : 0.0f;
    int chunk = k >> 6, kin = k & 63, s = kin >> 4, kk = kin & 15;
    int tig = kk >> 2, rg = (kk >> 1) & 1, hf = kk & 1;
    int nt = n >> 3, pr = nt >> 1, e = nt & 1;
    int tl = (n & 7) * 4 + tig;
    int o = chunk * 16384 + s * 4096 + pr * 256 + tl * 8 + e * 4 + rg * 2 + hf;
    g_Wh[o] = __float2half_rn(v);
}
// leaf[k][n] (256 leaves x 128 dout) -> frag-linear fp16 single, paired n-tiles
__global__ void prep_leaf(const float* __restrict__ L) {
    int idx = blockIdx.x * 256 + threadIdx.x;
    int k = idx >> 7, n = idx & 127;
    float v = L[k * 128 + n];
    int s = k >> 4, kk = k & 15;
    int nt = n >> 3, pr = nt >> 1, e = nt & 1;
    int tl = (n & 7) * 4 + ((kk >> 1) & 3), rg = kk >> 3, hf = kk & 1;
    int o = s * 2048 + pr * 256 + tl * 8 + e * 4 + rg * 2 + hf;
    g_Lhf[o] = __float2half_rn(v);
}
__global__ void init_reg(float* regp) { *regp = 0.0f; }

__global__ void __launch_bounds__(256, 2) tree_main(
    const float* __restrict__ x, const float* __restrict__ bsp,
    float* __restrict__ out, float* __restrict__ regp)
{
    extern __shared__ char smc[];
    __shared__ float s_bias[256];
    __shared__ float s_racc;
    const uint32_t sb = smem_u32(smc);

    const int tid = threadIdx.x, lane = tid & 31, w = tid >> 5;
    const int mwarp = w & 1, nwarp = w >> 1;          // 32-row x 64-col warp tile
    const int m0 = blockIdx.x * 64;

    s_bias[tid] = (tid < 255) ? bsp[tid] : 0.0f;
    if (tid == 0) s_racc = 0.0f;

    float acc[2][8][4] = {};

    // A staging slot decomposition: thread owns slots (a0=w, lane) and (a0+8, lane)
    // slot (a,l): s = a>>2, mblk = a&3, row = mblk*16 + (l>>2) [and +8], kb = s*16 + (l&3)*4
    const int sA0 = w, sA1 = w + 8;
    const int srow0 = (sA0 & 3) * 16 + (lane >> 2);
    const int srow1 = (sA1 & 3) * 16 + (lane >> 2);
    const int skb0 = (sA0 >> 2) * 16 + (lane & 3) * 4;
    const int skb1 = (sA1 >> 2) * 16 + (lane & 3) * 4;
    const float* xr0a = x + (size_t)(m0 + srow0) * 1024 + skb0;
    const float* xr0b = x + (size_t)(m0 + srow0 + 8) * 1024 + skb0;
    const float* xr1a = x + (size_t)(m0 + srow1) * 1024 + skb1;
    const float* xr1b = x + (size_t)(m0 + srow1 + 8) * 1024 + skb1;
    const uint32_t stsA0 = sb + sA0 * 512 + lane * 16;
    const uint32_t stsA1 = sb + sA1 * 512 + lane * 16;

    // ---- prologue: stage chunk 0 ----
    {
        float4 v0a = *(const float4*)xr0a, v0b = *(const float4*)xr0b;
        float4 v1a = *(const float4*)xr1a, v1b = *(const float4*)xr1b;
        uint4 f0, f1;
        f0.x = pack_h2(v0a.x, v0a.y); f0.y = pack_h2(v0b.x, v0b.y);
        f0.z = pack_h2(v0a.z, v0a.w); f0.w = pack_h2(v0b.z, v0b.w);
        f1.x = pack_h2(v1a.x, v1a.y); f1.y = pack_h2(v1b.x, v1b.y);
        f1.z = pack_h2(v1a.z, v1a.w); f1.w = pack_h2(v1b.z, v1b.w);
        *(uint4*)(smc + sA0 * 512 + lane * 16) = f0;
        *(uint4*)(smc + sA1 * 512 + lane * 16) = f1;
        #pragma unroll
        for (int i = 0; i < 8; i++)
            cp16(sb + OFF_W + (tid + i * 256) * 16, (const char*)g_Wh + (tid + i * 256) * 16);
        CP_COMMIT();
        CP_WAIT0();
        __syncthreads();
    }

    // ---- GEMM1: 16 K64-chunks, double-buffered; A fp16 frags direct ----
    for (int c = 0; c < 16; c++) {
        const int st = c & 1, nst = st ^ 1;
        float4 v0a, v0b, v1a, v1b;
        if (c < 15) {
            int cb = (c + 1) * 64;
            v0a = *(const float4*)(xr0a + cb); v0b = *(const float4*)(xr0b + cb);
            v1a = *(const float4*)(xr1a + cb); v1b = *(const float4*)(xr1b + cb);
            const char* srcW = (const char*)g_Wh + (c + 1) * 32768;
            #pragma unroll
            for (int i = 0; i < 8; i++)
                cp16(sb + nst * STG + OFF_W + (tid + i * 256) * 16, srcW + (tid + i * 256) * 16);
            CP_COMMIT();
        }
        #pragma unroll
        for (int s = 0; s < 4; s++) {
            uint32_t ah[2][4];
            #pragma unroll
            for (int mt = 0; mt < 2; mt++) {
                const char* ap = smc + st * STG + (s * 4 + mwarp * 2 + mt) * 512 + lane * 16;
                *(uint4*)ah[mt] = *(const uint4*)ap;
            }
            #pragma unroll
            for (int ntp = 0; ntp < 4; ntp++) {
                const char* bp = smc + st * STG + OFF_W + s * 8192 + (nwarp * 4 + ntp) * 512 + lane * 16;
                uint4 bq = *(const uint4*)bp;
                mma_f16(acc[0][2 * ntp],     ah[0], bq.x, bq.y);
                mma_f16(acc[0][2 * ntp + 1], ah[0], bq.z, bq.w);
                mma_f16(acc[1][2 * ntp],     ah[1], bq.x, bq.y);
                mma_f16(acc[1][2 * ntp + 1], ah[1], bq.z, bq.w);
            }
        }
        if (c < 15) {
            uint4 f0, f1;
            f0.x = pack_h2(v0a.x, v0a.y); f0.y = pack_h2(v0b.x, v0b.y);
            f0.z = pack_h2(v0a.z, v0a.w); f0.w = pack_h2(v0b.z, v0b.w);
            f1.x = pack_h2(v1a.x, v1a.y); f1.y = pack_h2(v1b.x, v1b.y);
            f1.z = pack_h2(v1a.z, v1a.w); f1.w = pack_h2(v1b.z, v1b.w);
            *(uint4*)(smc + nst * STG + sA0 * 512 + lane * 16) = f0;
            *(uint4*)(smc + nst * STG + sA1 * 512 + lane * 16) = f1;
        }
        CP_WAIT0();
        __syncthreads();
    }

    // ---- prefetch leaf quarter 0, then sigmoid + reg; P -> SMEM fp32 ----
    #pragma unroll
    for (int i = 0; i < 4; i++)
        cp16(sb + OFF_LB + (tid + i * 256) * 16, (const char*)g_Lhf + (tid + i * 256) * 16);
    CP_COMMIT();

    float racc = 0.0f;
    float* Pf0 = (float*)smc;
    #pragma unroll
    for (int mt = 0; mt < 2; mt++)
        #pragma unroll
        for (int nt = 0; nt < 8; nt++)
            #pragma unroll
            for (int cc = 0; cc < 4; cc++) {
                int row = mwarp * 32 + mt * 16 + (lane >> 2) + ((cc >> 1) << 3);
                int col = nwarp * 64 + nt * 8 + 2 * (lane & 3) + (cc & 1);
                if (col < 255) {
                    float lg = acc[mt][nt][cc] + s_bias[col];
                    float p = 1.0f / (1.0f + __expf(-lg));
                    Pf0[row * PSTRF + col] = p;
                    int d = 31 - __clz(col + 1);
                    racc += __uint_as_float((uint32_t)(127 - d) << 23) *
                            __logf(fmaxf(p * (1.0f - p), 1e-5f));
                }
            }

    // ---- GEMM2: probs fp16 hi/lo (2-pass) x leaf fp16; 4 x 16KB quarters ----
    float acc2[8][4] = {};
    const int mwarp2 = w & 3, nwarp2 = w >> 2;
    const int la = lane & 3;
    #pragma unroll 1
    for (int qq = 0; qq < 4; qq++) {
        CP_WAIT0();
        __syncthreads();
        if (qq < 3) {
            uint32_t db = sb + OFF_LB + ((qq + 1) & 1) * 16384;
            const char* sh = (const char*)(g_Lhf + (qq + 1) * 8192);
            #pragma unroll
            for (int i = 0; i < 4; i++)
                cp16(db + (tid + i * 256) * 16, sh + (tid + i * 256) * 16);
            CP_COMMIT();
        }
        const char* LB = smc + OFF_LB + (qq & 1) * 16384;
        #pragma unroll
        for (int sl2 = 0; sl2 < 4; sl2++) {
            int s = qq * 4 + sl2;
            int jA = 8 * s + la, jB = jA + 4;
            uint32_t ah[4], al4[4];
            #pragma unroll
            for (int rr = 0; rr < 2; rr++) {
                int row = mwarp2 * 16 + (lane >> 2) + rr * 8;
                const float* Pf = Pf0 + row * PSTRF;
                float pv, pre;
                pv = Pf[s >> 4];       pre  = ((s >> 3) & 1) ? pv : 1.0f - pv;
                pv = Pf[1 + (s >> 3)]; pre *= ((s >> 2) & 1) ? pv : 1.0f - pv;
                pv = Pf[3 + (s >> 2)]; pre *= ((s >> 1) & 1) ? pv : 1.0f - pv;
                pv = Pf[7 + (s >> 1)]; pre *= (s & 1) ? pv : 1.0f - pv;
                float p4 = Pf[15 + s];
                float preA = pre * (1.0f - p4), preB = pre * p4;
                int b5 = (la >> 1) & 1, b6 = la & 1;
                float p5a = Pf[31 + 2 * s];
                float p5b = Pf[31 + 2 * s + 1];
                preA *= b5 ? p5a : 1.0f - p5a;
                preB *= b5 ? p5b : 1.0f - p5b;
                float p6a = Pf[63 + (jA >> 1)];
                float p6b = Pf[63 + (jB >> 1)];
                preA *= b6 ? p6a : 1.0f - p6a;
                preB *= b6 ? p6b : 1.0f - p6b;
                float p7a = Pf[127 + jA];
                float p7b = Pf[127 + jB];
                split_h(preA * (1.0f - p7a), preA * p7a, ah[rr], al4[rr]);
                split_h(preB * (1.0f - p7b), preB * p7b, ah[2 + rr], al4[2 + rr]);
            }
            #pragma unroll
            for (int np = 0; np < 2; np++) {
                const char* bp0 = LB + sl2 * 4096 + (nwarp2 * 4 + 2 * np) * 512 + lane * 16;
                uint4 bh0 = *(const uint4*)bp0;
                uint4 bh1 = *(const uint4*)(bp0 + 512);
                float* a0 = acc2[4 * np + 0];
                float* a1 = acc2[4 * np + 1];
                float* a2 = acc2[4 * np + 2];
                float* a3 = acc2[4 * np + 3];
                mma_f16(a0, ah, bh0.x, bh0.y);
                mma_f16(a1, ah, bh0.z, bh0.w);
                mma_f16(a2, ah, bh1.x, bh1.y);
                mma_f16(a3, ah, bh1.z, bh1.w);
                mma_f16(a0, al4, bh0.x, bh0.y);
                mma_f16(a1, al4, bh0.z, bh0.w);
                mma_f16(a2, al4, bh1.x, bh1.y);
                mma_f16(a3, al4, bh1.z, bh1.w);
            }
        }
    }
    __syncthreads();   // all P reads done

    // ---- output bounce (coalesce) ----
    float* ob = (float*)smc;    // [64][132]
    #pragma unroll
    for (int nt = 0; nt < 8; nt++)
        #pragma unroll
        for (int cc = 0; cc < 4; cc++) {
            int row = mwarp2 * 16 + (lane >> 2) + ((cc >> 1) << 3);
            int col = nwarp2 * 64 + nt * 8 + 2 * (lane & 3) + (cc & 1);
            ob[row * 132 + col] = acc2[nt][cc];
        }
    __syncthreads();
    #pragma unroll
    for (int i = 0; i < 8; i++) {
        int e = tid + i * 256;
        int rr = e >> 5, cq = e & 31;
        *(float4*)(out + (size_t)(m0 + rr) * 128 + cq * 4) = *(const float4*)(ob + rr * 132 + cq * 4);
    }

    // ---- regularizer reduction ----
    #pragma unroll
    for (int o = 16; o; o >>= 1) racc += __shfl_xor_sync(0xFFFFFFFFu, racc, o);
    if (lane == 0) atomicAdd(&s_racc, racc);
    __syncthreads();
    if (tid == 0) atomicAdd(regp, s_racc * (-0.5f / 65536.0f));
}

extern "C" void kernel_launch(void* const* d_in, const int* in_sizes, int n_in,
                              void* d_out, int out_size) {
    const float* x    = (const float*)d_in[0];
    const float* W    = (const float*)d_in[1];
    const float* bsp  = (const float*)d_in[2];
    const float* leaf = (const float*)d_in[3];
    float* out  = (float*)d_out;
    float* regp = out + (out_size - 1);
    cudaFuncSetAttribute(tree_main, cudaFuncAttributeMaxDynamicSharedMemorySize, SMEM_DYN);
    init_reg<<<1, 1>>>(regp);
    prep_w<<<1024, 256>>>(W);
    prep_leaf<<<128, 256>>>(leaf);
    tree_main<<<1024, 256, SMEM_DYN>>>(x, bsp, out, regp);
}